// round 1
// baseline (speedup 1.0000x reference)
#include <cuda_runtime.h>
#include <cuda_bf16.h>
#include <math.h>

// Problem constants
#define BB 32
#define TT 2048
#define DD 256
#define HH 128

// Scratch for input projection: xp0[t][b][h]  (33.5 MB, device global = allowed scratch)
__device__ float g_xp0[(size_t)TT * BB * HH];

// ---------------------------------------------------------------------------
// Kernel A: xp0[t][b][j] = sum_k x[b][t][k] * W_ih0[j][k] + b_ih0[j] + b_hh0[j]
// One block per t. 256 threads: thread covers 4 j x 4 b register tile.
// ---------------------------------------------------------------------------
__global__ __launch_bounds__(256) void input_proj_kernel(
    const float* __restrict__ x,
    const float* __restrict__ W_ih0,
    const float* __restrict__ b_ih0,
    const float* __restrict__ b_hh0)
{
    __shared__ float xs[BB][64];        // [b][k-chunk]   8 KB
    __shared__ float ws[64][HH];        // [k][j] transposed -> conflict-free  32 KB

    const int t   = blockIdx.x;
    const int tid = threadIdx.x;
    const int jg  = (tid & 31) * 4;     // j0 in {0,4,...,124}
    const int bg  = (tid >> 5) * 4;     // b0 in {0,4,...,28}

    float acc[4][4];
#pragma unroll
    for (int i = 0; i < 4; i++)
#pragma unroll
        for (int k = 0; k < 4; k++) acc[i][k] = 0.f;

    for (int k0 = 0; k0 < DD; k0 += 64) {
        // load x tile: 32 rows x 64 floats (float4 granularity)
        for (int i = tid; i < BB * 16; i += 256) {
            int b  = i >> 4;
            int kk = (i & 15) * 4;
            *(float4*)&xs[b][kk] =
                *(const float4*)&x[((size_t)b * TT + t) * DD + k0 + kk];
        }
        // load W chunk transposed: ws[k][j] = W_ih0[j][k0+k]
        for (int i = tid; i < HH * 16; i += 256) {
            int j  = i >> 4;
            int kk = (i & 15) * 4;
            float4 w = *(const float4*)&W_ih0[(size_t)j * DD + k0 + kk];
            ws[kk + 0][j] = w.x;
            ws[kk + 1][j] = w.y;
            ws[kk + 2][j] = w.z;
            ws[kk + 3][j] = w.w;
        }
        __syncthreads();

#pragma unroll 16
        for (int k = 0; k < 64; k++) {
            float4 wv = *(const float4*)&ws[k][jg];   // conflict-free across warp
            float x0 = xs[bg + 0][k];                 // broadcast
            float x1 = xs[bg + 1][k];
            float x2 = xs[bg + 2][k];
            float x3 = xs[bg + 3][k];
            acc[0][0] += wv.x * x0; acc[0][1] += wv.y * x0;
            acc[0][2] += wv.z * x0; acc[0][3] += wv.w * x0;
            acc[1][0] += wv.x * x1; acc[1][1] += wv.y * x1;
            acc[1][2] += wv.z * x1; acc[1][3] += wv.w * x1;
            acc[2][0] += wv.x * x2; acc[2][1] += wv.y * x2;
            acc[2][2] += wv.z * x2; acc[2][3] += wv.w * x2;
            acc[3][0] += wv.x * x3; acc[3][1] += wv.y * x3;
            acc[3][2] += wv.z * x3; acc[3][3] += wv.w * x3;
        }
        __syncthreads();
    }

    // write out with bias
#pragma unroll
    for (int jj = 0; jj < 4; jj++) {
        float bias = b_ih0[jg + jj] + b_hh0[jg + jj];
#pragma unroll
        for (int bb2 = 0; bb2 < 4; bb2++) {
            g_xp0[((size_t)t * BB + (bg + bb2)) * HH + jg + jj] = acc[bb2][jj] + bias;
        }
    }
}

// ---------------------------------------------------------------------------
// Kernel B: the recurrence. One CTA per batch element (32 CTAs).
// 512 threads: tid = c*128 + j ; c in 0..3 is a 32-wide k-chunk, j is output.
// Weight-stationary: each thread holds W_hh0[j][32c..+32), W_ih1[j][...],
// W_hh1[j][...] in registers (96 regs).  h broadcast via float4 LDS.
//
// Per step:
//   Phase A: partials of W_hh0 @ h0  and  W_hh1 @ h1   (h1 is prev step -> parallel)
//   Reduce A (warps 0-3): h0n = tanh(xp + sum) ; (warps 4-7): s1 = sum(hh1 partials)
//   Phase B: partials of W_ih1 @ h0n
//   Reduce B: h1n = tanh(s1 + bias + sum) ; store to out
// ---------------------------------------------------------------------------
__global__ void __launch_bounds__(512, 1) rnn_rec_kernel(
    const float* __restrict__ W_hh0,
    const float* __restrict__ W_ih1,
    const float* __restrict__ W_hh1,
    const float* __restrict__ b_ih1,
    const float* __restrict__ b_hh1,
    float* __restrict__ out)
{
    const int bidx = blockIdx.x;       // batch element
    const int tid  = threadIdx.x;
    const int j    = tid & 127;
    const int c    = tid >> 7;         // 0..3

    __shared__ float h0s[HH];
    __shared__ float h1s[HH];
    __shared__ float s1s[HH];
    __shared__ float bias[HH];
    __shared__ float ps0[4][HH];
    __shared__ float ps1[4][HH];
    __shared__ float ps2[4][HH];

    // load weights into registers
    float4 w0[8], w1[8], w2[8];
    {
        const float4* p0 = (const float4*)&W_hh0[(size_t)j * HH + c * 32];
        const float4* p1 = (const float4*)&W_ih1[(size_t)j * HH + c * 32];
        const float4* p2 = (const float4*)&W_hh1[(size_t)j * HH + c * 32];
#pragma unroll
        for (int i = 0; i < 8; i++) { w0[i] = p0[i]; w1[i] = p1[i]; w2[i] = p2[i]; }
    }

    if (tid < HH) {
        h0s[tid]  = 0.f;
        h1s[tid]  = 0.f;
        bias[tid] = b_ih1[tid] + b_hh1[tid];
    }
    __syncthreads();

    const float* xpb  = g_xp0 + (size_t)bidx * HH;           // xp[t][bidx][:]
    float*       outb = out + (size_t)bidx * TT * HH;        // out[bidx][t][:]

    float xpr = (tid < HH) ? xpb[j] : 0.f;                   // prefetch t=0

    const float4* h0v = (const float4*)&h0s[c * 32];
    const float4* h1v = (const float4*)&h1s[c * 32];

    for (int t = 0; t < TT; t++) {
        // ---- Phase A: W_hh0 @ h0  and  W_hh1 @ h1 (prev) partials ----
        float a0 = 0.f, a1 = 0.f;
#pragma unroll
        for (int i = 0; i < 8; i++) {
            float4 h = h0v[i];   // broadcast within warp
            a0 += w0[i].x * h.x + w0[i].y * h.y + w0[i].z * h.z + w0[i].w * h.w;
            float4 g = h1v[i];
            a1 += w2[i].x * g.x + w2[i].y * g.y + w2[i].z * g.z + w2[i].w * g.w;
        }
        ps0[c][j] = a0;
        ps1[c][j] = a1;
        __syncthreads();

        // ---- Reduce A ----
        if (tid < HH) {
            float h0n = tanhf(xpr + ps0[0][j] + ps0[1][j] + ps0[2][j] + ps0[3][j]);
            h0s[j] = h0n;
            if (t + 1 < TT)
                xpr = xpb[(size_t)(t + 1) * BB * HH + j];    // prefetch next step
        } else if (tid < 2 * HH) {
            s1s[j] = ps1[0][j] + ps1[1][j] + ps1[2][j] + ps1[3][j];
        }
        __syncthreads();

        // ---- Phase B: W_ih1 @ h0n partials ----
        float b0 = 0.f;
#pragma unroll
        for (int i = 0; i < 8; i++) {
            float4 h = h0v[i];   // now holds h0n
            b0 += w1[i].x * h.x + w1[i].y * h.y + w1[i].z * h.z + w1[i].w * h.w;
        }
        ps2[c][j] = b0;
        __syncthreads();

        // ---- Reduce B ----
        if (tid < HH) {
            float h1n = tanhf(s1s[j] + bias[j] +
                              ps2[0][j] + ps2[1][j] + ps2[2][j] + ps2[3][j]);
            h1s[j] = h1n;
            outb[(size_t)t * HH + j] = h1n;
        }
        __syncthreads();
    }
}

// ---------------------------------------------------------------------------
// Launch
// ---------------------------------------------------------------------------
extern "C" void kernel_launch(void* const* d_in, const int* in_sizes, int n_in,
                              void* d_out, int out_size)
{
    const float* x     = (const float*)d_in[0];
    const float* W_ih0 = (const float*)d_in[1];
    const float* W_hh0 = (const float*)d_in[2];
    const float* b_ih0 = (const float*)d_in[3];
    const float* b_hh0 = (const float*)d_in[4];
    const float* W_ih1 = (const float*)d_in[5];
    const float* W_hh1 = (const float*)d_in[6];
    const float* b_ih1 = (const float*)d_in[7];
    const float* b_hh1 = (const float*)d_in[8];
    float* out = (float*)d_out;

    input_proj_kernel<<<TT, 256>>>(x, W_ih0, b_ih0, b_hh0);
    rnn_rec_kernel<<<BB, 512>>>(W_hh0, W_ih1, W_hh1, b_ih1, b_hh1, out);
}